// round 5
// baseline (speedup 1.0000x reference)
#include <cuda_runtime.h>
#include <cuda_bf16.h>
#include <cstdint>

// Problem dims (fixed by the reference)
#define BB 16
#define TT 128
#define HH 512
#define VV 32000
#define G4 2048   // 4*H

// ---------------- device scratch (static: no allocation allowed) -----------
__device__ __nv_bfloat16 g_Xh   [TT*BB*HH];  // x embeddings, bf16 hi
__device__ __nv_bfloat16 g_Xl   [TT*BB*HH];  // x embeddings, bf16 lo
__device__ __nv_bfloat16 g_Wih_h[G4*HH];
__device__ __nv_bfloat16 g_Wih_l[G4*HH];
__device__ __nv_bfloat16 g_Wout_h[(size_t)VV*HH];
__device__ __nv_bfloat16 g_Wout_l[(size_t)VV*HH];
__device__ __nv_bfloat16 g_Hh   [TT*BB*HH];  // hidden states bf16 hi
__device__ __nv_bfloat16 g_Hl   [TT*BB*HH];  // hidden states bf16 lo
__device__ float    g_Xg[TT*BB*G4];   // x@W_ih^T + b_ih + b_hh (f32)
__device__ float    g_Hs[TT*BB*HH];   // hidden states f32 (for recurrence)
__device__ float    g_bias[G4];       // b_ih + b_hh
__device__ unsigned char g_flag[TT*128];  // per-step per-CTA completion flags

// ---------------- helpers --------------------------------------------------
__device__ __forceinline__ float sigm(float x) { return 1.0f / (1.0f + expf(-x)); }

__device__ __forceinline__ uint32_t smem_u32(const void* p) {
    uint32_t a;
    asm("{ .reg .u64 t; cvta.to.shared.u64 t, %1; cvt.u32.u64 %0, t; }" : "=r"(a) : "l"(p));
    return a;
}
__device__ __forceinline__ uint32_t sw128(uint32_t b) { return b ^ ((b >> 3) & 0x70); }

__device__ __forceinline__ void cpasync16(uint32_t dst, const void* src) {
    asm volatile("cp.async.cg.shared.global [%0], [%1], 16;" :: "r"(dst), "l"(src) : "memory");
}
__device__ __forceinline__ void cp_commit() { asm volatile("cp.async.commit_group;" ::: "memory"); }
template<int N> __device__ __forceinline__ void cp_wait() {
    asm volatile("cp.async.wait_group %0;" :: "n"(N) : "memory");
}

__device__ __forceinline__ void ldsm4(uint32_t* r, uint32_t addr) {
    asm volatile("ldmatrix.sync.aligned.m8n8.x4.shared.b16 {%0,%1,%2,%3}, [%4];"
                 : "=r"(r[0]), "=r"(r[1]), "=r"(r[2]), "=r"(r[3]) : "r"(addr));
}
__device__ __forceinline__ void ldsm2(uint32_t* r, uint32_t addr) {
    asm volatile("ldmatrix.sync.aligned.m8n8.x2.shared.b16 {%0,%1}, [%2];"
                 : "=r"(r[0]), "=r"(r[1]) : "r"(addr));
}
__device__ __forceinline__ void mma16816(float* c, const uint32_t* a, const uint32_t* b) {
    asm volatile("mma.sync.aligned.m16n8k16.row.col.f32.bf16.bf16.f32 "
                 "{%0,%1,%2,%3}, {%4,%5,%6,%7}, {%8,%9}, {%0,%1,%2,%3};"
                 : "+f"(c[0]), "+f"(c[1]), "+f"(c[2]), "+f"(c[3])
                 : "r"(a[0]), "r"(a[1]), "r"(a[2]), "r"(a[3]), "r"(b[0]), "r"(b[1]));
}

// split one float4 into packed bf16 hi/lo pairs
__device__ __forceinline__ void split4(float4 v, uint2& hi, uint2& lo) {
    float xs[4] = {v.x, v.y, v.z, v.w};
    unsigned h[4], l[4];
#pragma unroll
    for (int q = 0; q < 4; q++) {
        __nv_bfloat16 hb = __float2bfloat16(xs[q]);
        __nv_bfloat16 lb = __float2bfloat16(xs[q] - __bfloat162float(hb));
        h[q] = *(unsigned short*)&hb;
        l[q] = *(unsigned short*)&lb;
    }
    hi.x = h[0] | (h[1] << 16); hi.y = h[2] | (h[3] << 16);
    lo.x = l[0] | (l[1] << 16); lo.y = l[2] | (l[3] << 16);
}

// ---------------- kernel 1: embedding gather + bf16 split -----------------
__global__ void k_gather(const int* __restrict__ xs, const float* __restrict__ emb) {
    int f = blockIdx.x * 256 + threadIdx.x;          // float4 id, 2048*128 total
    int row = f >> 7;
    int e   = (f & 127) << 2;
    int t = row >> 4, b = row & 15;
    int tok = xs[b * TT + t];
    float4 v = *(const float4*)&emb[(size_t)tok * HH + e];
    uint2 hi, lo; split4(v, hi, lo);
    *(uint2*)&g_Xh[row * HH + e] = hi;
    *(uint2*)&g_Xl[row * HH + e] = lo;
}

// ---------------- kernel 2: bias sum + flag reset -------------------------
__global__ void k_prep(const float* __restrict__ b_ih, const float* __restrict__ b_hh) {
    int i = blockIdx.x * 256 + threadIdx.x;
    if (i < G4) g_bias[i] = b_ih[i] + b_hh[i];
    if (i < TT * 128 / 16) ((uint4*)g_flag)[i] = make_uint4(0u, 0u, 0u, 0u);
}

// ---------------- kernel 3: weight bf16 hi/lo conversion ------------------
__global__ void k_conv(const float* __restrict__ W_ih, const float* __restrict__ W_out) {
    int i4 = blockIdx.x * 256 + threadIdx.x;
    const int NIH = G4 * HH / 4;          // 262144 float4s
    if (i4 < NIH) {
        float4 v = *(const float4*)&W_ih[(size_t)i4 * 4];
        uint2 h, l; split4(v, h, l);
        *(uint2*)&g_Wih_h[(size_t)i4 * 4] = h;
        *(uint2*)&g_Wih_l[(size_t)i4 * 4] = l;
    } else {
        size_t j = (size_t)(i4 - NIH);    // < 4,096,000
        float4 v = *(const float4*)&W_out[j * 4];
        uint2 h, l; split4(v, h, l);
        *(uint2*)&g_Wout_h[j * 4] = h;
        *(uint2*)&g_Wout_l[j * 4] = l;
    }
}

// ---------------- kernel 4: pipelined bf16x3 mma.sync GEMM ----------------
// C[n][m] = dot(A[n,:], B[m,:]) + bias[m], K = 512.
// Tile 128(n) x 128(m), BK = 64 bf16 (128B rows, sw128 smem), 3-stage
// cp.async pipeline (next chunk issued BEFORE compute), double-buffered
// ldmatrix fragments; 3 mma per pair: AhBh + AhBl + AlBh (fp32 accum).
#define KC 64
#define ST_AH 0
#define ST_AL 16384
#define ST_BH 32768
#define ST_BL 49152
#define STAGE_BYTES 65536
#define NSTAGE 3
#define GSMEM (NSTAGE * STAGE_BYTES)    // 192 KB

__global__ void __launch_bounds__(256, 1) gemm_tc(
    const __nv_bfloat16* __restrict__ Ah, const __nv_bfloat16* __restrict__ Al,
    const __nv_bfloat16* __restrict__ Bh, const __nv_bfloat16* __restrict__ Bl,
    const float* __restrict__ bias, float* __restrict__ C, int M)
{
    extern __shared__ char smem[];
    const uint32_t sb = smem_u32(smem);
    const int tid  = threadIdx.x;
    const int lane = tid & 31, wid = tid >> 5;
    const int warp_n = wid >> 2;          // 0..1 -> 64-row slab (A rows)
    const int warp_m = wid & 3;           // 0..3 -> 32-row slab (B rows)
    const int n0 = blockIdx.y * 128;
    const int m0 = blockIdx.x * 128;

    float c[4][4][4];
#pragma unroll
    for (int i = 0; i < 4; i++)
#pragma unroll
        for (int j = 0; j < 4; j++)
#pragma unroll
            for (int q = 0; q < 4; q++) c[i][j][q] = 0.0f;

    // per-lane ldmatrix source coordinates
    const int a_lr = lane & 7, a_sel = lane >> 3;
    const int a_row = (a_sel & 1) * 8 + a_lr;     // within 16-row tile
    const int a_col = (a_sel >> 1) * 8;           // 0 or 8
    const int b_l   = lane & 15;
    const int b_row = b_l & 7;                    // within 8-row tile
    const int b_col = (b_l >> 3) * 8;             // 0 or 8

    // ---- async chunk loader: 16 cp.async(16B) per thread per chunk ----
    auto load_chunk = [&](int cc) {
        const uint32_t sbase = sb + (uint32_t)(cc % NSTAGE) * STAGE_BYTES;
        const int kb = cc * KC;
#pragma unroll
        for (int i = 0; i < 4; i++) {
            int idx = tid + i * 256;               // 0..1023
            int row = idx >> 3, seg = idx & 7;     // 128 rows x 8 16B-segs
            uint32_t sw = sw128((uint32_t)(row * 128 + seg * 16));
            size_t goa = (size_t)(n0 + row) * HH + kb + seg * 8;
            size_t gob = (size_t)(m0 + row) * HH + kb + seg * 8;
            cpasync16(sbase + ST_AH + sw, Ah + goa);
            cpasync16(sbase + ST_AL + sw, Al + goa);
            cpasync16(sbase + ST_BH + sw, Bh + gob);
            cpasync16(sbase + ST_BL + sw, Bl + gob);
        }
        cp_commit();
    };

    // fragment double buffers
    uint32_t ah[2][4][4], al[2][4][4], bh[2][4][2], bl[2][4][2];
    auto ldfrag = [&](int buf, uint32_t sbase, int kk) {
#pragma unroll
        for (int i = 0; i < 4; i++) {
            int r = warp_n * 64 + i * 16 + a_row;
            uint32_t sw = sw128((uint32_t)(r * 128 + (kk + a_col) * 2));
            ldsm4(ah[buf][i], sbase + ST_AH + sw);
            ldsm4(al[buf][i], sbase + ST_AL + sw);
        }
#pragma unroll
        for (int j = 0; j < 4; j++) {
            int r = warp_m * 32 + j * 8 + b_row;
            uint32_t sw = sw128((uint32_t)(r * 128 + (kk + b_col) * 2));
            ldsm2(bh[buf][j], sbase + ST_BH + sw);
            ldsm2(bl[buf][j], sbase + ST_BL + sw);
        }
    };

    load_chunk(0);
    load_chunk(1);

#pragma unroll 1
    for (int cc = 0; cc < 8; cc++) {
        if (cc < 7) cp_wait<1>(); else cp_wait<0>();
        __syncthreads();
        if (cc + 2 < 8) load_chunk(cc + 2);     // overlap loads with compute
        const uint32_t sbase = sb + (uint32_t)(cc % NSTAGE) * STAGE_BYTES;

        ldfrag(0, sbase, 0);
#pragma unroll
        for (int ki = 0; ki < 4; ki++) {
            if (ki < 3) ldfrag((ki + 1) & 1, sbase, (ki + 1) * 16);
            const int bf = ki & 1;
#pragma unroll
            for (int i = 0; i < 4; i++)
#pragma unroll
                for (int j = 0; j < 4; j++) {
                    mma16816(c[i][j], ah[bf][i], bh[bf][j]);
                    mma16816(c[i][j], ah[bf][i], bl[bf][j]);
                    mma16816(c[i][j], al[bf][i], bh[bf][j]);
                }
        }
    }

    // ---- epilogue: add bias, store f32 ----------
#pragma unroll
    for (int i = 0; i < 4; i++) {
        int n = n0 + warp_n * 64 + i * 16 + (lane >> 2);
#pragma unroll
        for (int j = 0; j < 4; j++) {
            int m = m0 + warp_m * 32 + j * 8 + ((lane & 3) << 1);
            float bx = bias[m], by = bias[m + 1];
            *(float2*)&C[(size_t)n * M + m]       = make_float2(c[i][j][0] + bx, c[i][j][1] + by);
            *(float2*)&C[(size_t)(n + 8) * M + m] = make_float2(c[i][j][2] + bx, c[i][j][3] + by);
        }
    }
}

// ---------------- kernel 5: persistent LSTM -------------------------------
// 128 CTAs x 128 threads, grid co-resident (128 <= 148 SMs) -> safe barrier.
// Barrier v2: per-CTA flag bytes (no atomic serialization), warp-0 hot spin.
__global__ void __launch_bounds__(128) k_lstm(const float* __restrict__ enc_h,
                                              const float* __restrict__ enc_c,
                                              const float* __restrict__ W_hh) {
    extern __shared__ float sm[];
    float* w_sh    = sm;                 // [16][516]
    float* h_sh    = sm + 16 * 516;      // [16][516]  (b-major)
    float* c_sh    = sm + 32 * 516;      // [4][16]    (jj, b)
    float* gate_sh = c_sh + 64;          // [16][16]   (rl = gate*4+jj, b)

    const int cb  = blockIdx.x;
    const int tid = threadIdx.x;

    for (int f = tid; f < 2048; f += 128) {
        int rl = f >> 7, k4 = (f & 127) << 2;
        int grow = (rl >> 2) * HH + cb * 4 + (rl & 3);
        *(float4*)&w_sh[rl * 516 + k4] = *(const float4*)&W_hh[(size_t)grow * HH + k4];
    }
    if (tid < 64) {
        int jj = tid >> 4, b = tid & 15;
        c_sh[jj * 16 + b] = enc_c[b * HH + cb * 4 + jj];
    }
    __syncthreads();

    const int rp = tid >> 4;
    const int b  = tid & 15;
    const int r0 = rp * 2, r1 = r0 + 1;
    const int g0 = r0 >> 2, j0 = r0 & 3;
    const int g1 = r1 >> 2, j1 = r1 & 3;

    for (int t = 0; t < TT; t++) {
        const float* hsrc = (t == 0) ? enc_h : &g_Hs[(size_t)(t - 1) * BB * HH];
        for (int f = tid; f < 2048; f += 128) {
            int bb = f >> 7, k4 = (f & 127) << 2;
            *(float4*)&h_sh[bb * 516 + k4] = *(const float4*)&hsrc[bb * HH + k4];
        }
        __syncthreads();

        float acc0 = g_Xg[(size_t)(t * BB + b) * G4 + g0 * HH + cb * 4 + j0];
        float acc1 = g_Xg[(size_t)(t * BB + b) * G4 + g1 * HH + cb * 4 + j1];
        const float* hp = &h_sh[b * 516];
        const float* w0 = &w_sh[r0 * 516];
        const float* w1 = &w_sh[r1 * 516];
#pragma unroll 8
        for (int k = 0; k < HH; k += 4) {
            float4 hv = *(const float4*)&hp[k];
            float4 wa = *(const float4*)&w0[k];
            float4 wb = *(const float4*)&w1[k];
            acc0 += hv.x * wa.x + hv.y * wa.y + hv.z * wa.z + hv.w * wa.w;
            acc1 += hv.x * wb.x + hv.y * wb.y + hv.z * wb.z + hv.w * wb.w;
        }
        gate_sh[r0 * 16 + b] = acc0;
        gate_sh[r1 * 16 + b] = acc1;
        __syncthreads();

        if (tid < 64) {
            int jj = tid >> 4, bb = tid & 15;
            float iv = sigm (gate_sh[(0 * 4 + jj) * 16 + bb]);
            float fv = sigm (gate_sh[(1 * 4 + jj) * 16 + bb]);
            float gv = tanhf(gate_sh[(2 * 4 + jj) * 16 + bb]);
            float ov = sigm (gate_sh[(3 * 4 + jj) * 16 + bb]);
            float cc = fv * c_sh[jj * 16 + bb] + iv * gv;
            c_sh[jj * 16 + bb] = cc;
            float hv = ov * tanhf(cc);
            int hidx = (t * BB + bb) * HH + cb * 4 + jj;
            g_Hs[hidx] = hv;
            __nv_bfloat16 hb = __float2bfloat16(hv);
            g_Hh[hidx] = hb;
            g_Hl[hidx] = __float2bfloat16(hv - __bfloat162float(hb));
        }
        if (t == TT - 1) break;          // no consumer inside this kernel

        // ---- grid barrier v2: flag bytes + warp ballot spin ----
        __threadfence();                 // release my stores
        __syncthreads();                 // all threads' stores fenced
        if (tid == 0)
            ((volatile unsigned char*)g_flag)[t * 128 + cb] = 1;
        if (tid < 32) {
            volatile unsigned* fp = (volatile unsigned*)(g_flag + t * 128);
            while (!__all_sync(0xFFFFFFFFu, fp[tid] == 0x01010101u)) { }
            __threadfence();             // acquire
        }
        __syncthreads();
    }
}

// ---------------- launcher -------------------------------------------------
extern "C" void kernel_launch(void* const* d_in, const int* in_sizes, int n_in,
                              void* d_out, int out_size) {
    const int*   xs    = (const int*)  d_in[0];
    // d_in[1] = xs_len (unused by reference semantics)
    const float* enc_h = (const float*)d_in[2];
    const float* enc_c = (const float*)d_in[3];
    const float* emb   = (const float*)d_in[4];
    const float* W_ih  = (const float*)d_in[5];
    const float* W_hh  = (const float*)d_in[6];
    const float* b_ih  = (const float*)d_in[7];
    const float* b_hh  = (const float*)d_in[8];
    const float* W_out = (const float*)d_in[9];
    const float* b_out = (const float*)d_in[10];
    float* out = (float*)d_out;

    __nv_bfloat16 *pXh, *pXl, *pWih_h, *pWih_l, *pWout_h, *pWout_l, *pHh, *pHl;
    float *pXg, *pbias;
    cudaGetSymbolAddress((void**)&pXh,     g_Xh);
    cudaGetSymbolAddress((void**)&pXl,     g_Xl);
    cudaGetSymbolAddress((void**)&pWih_h,  g_Wih_h);
    cudaGetSymbolAddress((void**)&pWih_l,  g_Wih_l);
    cudaGetSymbolAddress((void**)&pWout_h, g_Wout_h);
    cudaGetSymbolAddress((void**)&pWout_l, g_Wout_l);
    cudaGetSymbolAddress((void**)&pHh,     g_Hh);
    cudaGetSymbolAddress((void**)&pHl,     g_Hl);
    cudaGetSymbolAddress((void**)&pXg,     g_Xg);
    cudaGetSymbolAddress((void**)&pbias,   g_bias);

    k_gather<<<1024, 256>>>(xs, emb);
    k_prep<<<8, 256>>>(b_ih, b_hh);
    k_conv<<<(G4*HH/4 + (int)((size_t)VV*HH/4)) / 256, 256>>>(W_ih, W_out);

    cudaFuncSetAttribute(gemm_tc, cudaFuncAttributeMaxDynamicSharedMemorySize, GSMEM);

    // Xg = X @ W_ih^T + (b_ih + b_hh)   [2048 x 2048]
    gemm_tc<<<dim3(G4 / 128, (TT * BB) / 128), 256, GSMEM>>>(
        pXh, pXl, pWih_h, pWih_l, pbias, pXg, G4);

    int lsmem = (2 * 16 * 516 + 64 + 256) * (int)sizeof(float);  // ~67 KB
    cudaFuncSetAttribute(k_lstm, cudaFuncAttributeMaxDynamicSharedMemorySize, lsmem);
    k_lstm<<<128, 128, lsmem>>>(enc_h, enc_c, W_hh);

    // logits = Hs @ W_out^T + b_out     [2048 x 32000]
    gemm_tc<<<dim3(VV / 128, (TT * BB) / 128), 256, GSMEM>>>(
        pHh, pHl, pWout_h, pWout_l, b_out, out, VV);
}

// round 8
// speedup vs baseline: 1.5542x; 1.5542x over previous
#include <cuda_runtime.h>
#include <cuda_bf16.h>
#include <cstdint>

// Problem dims (fixed by the reference)
#define BB 16
#define TT 128
#define HH 512
#define VV 32000
#define G4 2048   // 4*H

// ---------------- device scratch (static: no allocation allowed) -----------
__device__ __nv_bfloat16 g_Xh   [TT*BB*HH];  // x embeddings, bf16 hi
__device__ __nv_bfloat16 g_Xl   [TT*BB*HH];  // x embeddings, bf16 lo
__device__ __nv_bfloat16 g_Wih_h[G4*HH];
__device__ __nv_bfloat16 g_Wih_l[G4*HH];
__device__ __nv_bfloat16 g_Wout_h[(size_t)VV*HH];
__device__ __nv_bfloat16 g_Wout_l[(size_t)VV*HH];
__device__ __nv_bfloat16 g_Hh   [TT*BB*HH];  // hidden states bf16 hi
__device__ __nv_bfloat16 g_Hl   [TT*BB*HH];  // hidden states bf16 lo
__device__ float    g_Xg[TT*BB*G4];   // x@W_ih^T + b_ih + b_hh (f32)
__device__ float    g_Hs[TT*BB*HH];   // hidden states f32 (for recurrence)
__device__ float    g_C [BB*HH];      // cell state (persists across step launches)
__device__ float    g_bias[G4];       // b_ih + b_hh

// ---------------- helpers --------------------------------------------------
__device__ __forceinline__ float sigm(float x) { return 1.0f / (1.0f + expf(-x)); }

__device__ __forceinline__ uint32_t smem_u32(const void* p) {
    uint32_t a;
    asm("{ .reg .u64 t; cvta.to.shared.u64 t, %1; cvt.u32.u64 %0, t; }" : "=r"(a) : "l"(p));
    return a;
}
__device__ __forceinline__ uint32_t sw128(uint32_t b) { return b ^ ((b >> 3) & 0x70); }

__device__ __forceinline__ void cpasync16(uint32_t dst, const void* src) {
    asm volatile("cp.async.cg.shared.global [%0], [%1], 16;" :: "r"(dst), "l"(src) : "memory");
}
__device__ __forceinline__ void cp_commit() { asm volatile("cp.async.commit_group;" ::: "memory"); }
template<int N> __device__ __forceinline__ void cp_wait() {
    asm volatile("cp.async.wait_group %0;" :: "n"(N) : "memory");
}

__device__ __forceinline__ void ldsm4(uint32_t* r, uint32_t addr) {
    asm volatile("ldmatrix.sync.aligned.m8n8.x4.shared.b16 {%0,%1,%2,%3}, [%4];"
                 : "=r"(r[0]), "=r"(r[1]), "=r"(r[2]), "=r"(r[3]) : "r"(addr));
}
__device__ __forceinline__ void ldsm2(uint32_t* r, uint32_t addr) {
    asm volatile("ldmatrix.sync.aligned.m8n8.x2.shared.b16 {%0,%1}, [%2];"
                 : "=r"(r[0]), "=r"(r[1]) : "r"(addr));
}
__device__ __forceinline__ void mma16816(float* c, const uint32_t* a, const uint32_t* b) {
    asm volatile("mma.sync.aligned.m16n8k16.row.col.f32.bf16.bf16.f32 "
                 "{%0,%1,%2,%3}, {%4,%5,%6,%7}, {%8,%9}, {%0,%1,%2,%3};"
                 : "+f"(c[0]), "+f"(c[1]), "+f"(c[2]), "+f"(c[3])
                 : "r"(a[0]), "r"(a[1]), "r"(a[2]), "r"(a[3]), "r"(b[0]), "r"(b[1]));
}

// split one float4 into packed bf16 hi/lo pairs
__device__ __forceinline__ void split4(float4 v, uint2& hi, uint2& lo) {
    float xs[4] = {v.x, v.y, v.z, v.w};
    unsigned h[4], l[4];
#pragma unroll
    for (int q = 0; q < 4; q++) {
        __nv_bfloat16 hb = __float2bfloat16(xs[q]);
        __nv_bfloat16 lb = __float2bfloat16(xs[q] - __bfloat162float(hb));
        h[q] = *(unsigned short*)&hb;
        l[q] = *(unsigned short*)&lb;
    }
    hi.x = h[0] | (h[1] << 16); hi.y = h[2] | (h[3] << 16);
    lo.x = l[0] | (l[1] << 16); lo.y = l[2] | (l[3] << 16);
}

// ---------------- kernel 1: embedding gather + bf16 split -----------------
__global__ void k_gather(const int* __restrict__ xs, const float* __restrict__ emb) {
    int f = blockIdx.x * 256 + threadIdx.x;          // float4 id, 2048*128 total
    int row = f >> 7;
    int e   = (f & 127) << 2;
    int t = row >> 4, b = row & 15;
    int tok = xs[b * TT + t];
    float4 v = *(const float4*)&emb[(size_t)tok * HH + e];
    uint2 hi, lo; split4(v, hi, lo);
    *(uint2*)&g_Xh[row * HH + e] = hi;
    *(uint2*)&g_Xl[row * HH + e] = lo;
}

// ---------------- kernel 2: bias sum --------------------------------------
__global__ void k_prep(const float* __restrict__ b_ih, const float* __restrict__ b_hh) {
    int i = blockIdx.x * 256 + threadIdx.x;
    if (i < G4) g_bias[i] = b_ih[i] + b_hh[i];
}

// ---------------- kernel 3: weight bf16 hi/lo conversion ------------------
__global__ void k_conv(const float* __restrict__ W_ih, const float* __restrict__ W_out) {
    int i4 = blockIdx.x * 256 + threadIdx.x;
    const int NIH = G4 * HH / 4;          // 262144 float4s
    if (i4 < NIH) {
        float4 v = *(const float4*)&W_ih[(size_t)i4 * 4];
        uint2 h, l; split4(v, h, l);
        *(uint2*)&g_Wih_h[(size_t)i4 * 4] = h;
        *(uint2*)&g_Wih_l[(size_t)i4 * 4] = l;
    } else {
        size_t j = (size_t)(i4 - NIH);    // < 4,096,000
        float4 v = *(const float4*)&W_out[j * 4];
        uint2 h, l; split4(v, h, l);
        *(uint2*)&g_Wout_h[j * 4] = h;
        *(uint2*)&g_Wout_l[j * 4] = l;
    }
}

// ---------------- kernel 4: pipelined bf16x3 mma.sync GEMM ----------------
// (byte-identical to round-4/5 passing version)
#define KC 64
#define ST_AH 0
#define ST_AL 16384
#define ST_BH 32768
#define ST_BL 49152
#define STAGE_BYTES 65536
#define NSTAGE 3
#define GSMEM (NSTAGE * STAGE_BYTES)    // 192 KB

__global__ void __launch_bounds__(256, 1) gemm_tc(
    const __nv_bfloat16* __restrict__ Ah, const __nv_bfloat16* __restrict__ Al,
    const __nv_bfloat16* __restrict__ Bh, const __nv_bfloat16* __restrict__ Bl,
    const float* __restrict__ bias, float* __restrict__ C, int M)
{
    extern __shared__ char smem[];
    const uint32_t sb = smem_u32(smem);
    const int tid  = threadIdx.x;
    const int lane = tid & 31, wid = tid >> 5;
    const int warp_n = wid >> 2;
    const int warp_m = wid & 3;
    const int n0 = blockIdx.y * 128;
    const int m0 = blockIdx.x * 128;

    float c[4][4][4];
#pragma unroll
    for (int i = 0; i < 4; i++)
#pragma unroll
        for (int j = 0; j < 4; j++)
#pragma unroll
            for (int q = 0; q < 4; q++) c[i][j][q] = 0.0f;

    const int a_lr = lane & 7, a_sel = lane >> 3;
    const int a_row = (a_sel & 1) * 8 + a_lr;
    const int a_col = (a_sel >> 1) * 8;
    const int b_l   = lane & 15;
    const int b_row = b_l & 7;
    const int b_col = (b_l >> 3) * 8;

    auto load_chunk = [&](int cc) {
        const uint32_t sbase = sb + (uint32_t)(cc % NSTAGE) * STAGE_BYTES;
        const int kb = cc * KC;
#pragma unroll
        for (int i = 0; i < 4; i++) {
            int idx = tid + i * 256;
            int row = idx >> 3, seg = idx & 7;
            uint32_t sw = sw128((uint32_t)(row * 128 + seg * 16));
            size_t goa = (size_t)(n0 + row) * HH + kb + seg * 8;
            size_t gob = (size_t)(m0 + row) * HH + kb + seg * 8;
            cpasync16(sbase + ST_AH + sw, Ah + goa);
            cpasync16(sbase + ST_AL + sw, Al + goa);
            cpasync16(sbase + ST_BH + sw, Bh + gob);
            cpasync16(sbase + ST_BL + sw, Bl + gob);
        }
        cp_commit();
    };

    uint32_t ah[2][4][4], al[2][4][4], bh[2][4][2], bl[2][4][2];
    auto ldfrag = [&](int buf, uint32_t sbase, int kk) {
#pragma unroll
        for (int i = 0; i < 4; i++) {
            int r = warp_n * 64 + i * 16 + a_row;
            uint32_t sw = sw128((uint32_t)(r * 128 + (kk + a_col) * 2));
            ldsm4(ah[buf][i], sbase + ST_AH + sw);
            ldsm4(al[buf][i], sbase + ST_AL + sw);
        }
#pragma unroll
        for (int j = 0; j < 4; j++) {
            int r = warp_m * 32 + j * 8 + b_row;
            uint32_t sw = sw128((uint32_t)(r * 128 + (kk + b_col) * 2));
            ldsm2(bh[buf][j], sbase + ST_BH + sw);
            ldsm2(bl[buf][j], sbase + ST_BL + sw);
        }
    };

    load_chunk(0);
    load_chunk(1);

#pragma unroll 1
    for (int cc = 0; cc < 8; cc++) {
        if (cc < 7) cp_wait<1>(); else cp_wait<0>();
        __syncthreads();
        if (cc + 2 < 8) load_chunk(cc + 2);
        const uint32_t sbase = sb + (uint32_t)(cc % NSTAGE) * STAGE_BYTES;

        ldfrag(0, sbase, 0);
#pragma unroll
        for (int ki = 0; ki < 4; ki++) {
            if (ki < 3) ldfrag((ki + 1) & 1, sbase, (ki + 1) * 16);
            const int bf = ki & 1;
#pragma unroll
            for (int i = 0; i < 4; i++)
#pragma unroll
                for (int j = 0; j < 4; j++) {
                    mma16816(c[i][j], ah[bf][i], bh[bf][j]);
                    mma16816(c[i][j], ah[bf][i], bl[bf][j]);
                    mma16816(c[i][j], al[bf][i], bh[bf][j]);
                }
        }
    }

#pragma unroll
    for (int i = 0; i < 4; i++) {
        int n = n0 + warp_n * 64 + i * 16 + (lane >> 2);
#pragma unroll
        for (int j = 0; j < 4; j++) {
            int m = m0 + warp_m * 32 + j * 8 + ((lane & 3) << 1);
            float bx = bias[m], by = bias[m + 1];
            *(float2*)&C[(size_t)n * M + m]       = make_float2(c[i][j][0] + bx, c[i][j][1] + by);
            *(float2*)&C[(size_t)(n + 8) * M + m] = make_float2(c[i][j][2] + bx, c[i][j][3] + by);
        }
    }
}

// ---------------- kernel 5: ONE LSTM time step ----------------------------
// Launched 128 times (t = 0..127) inside the captured graph. Kernel-launch
// boundaries provide the cross-CTA ordering + visibility — no in-kernel grid
// barrier, no fences, no races. Cell state persists in g_C.
// CTA cb owns h-indices [cb*4, cb*4+4) = 16 gate rows; W slice + h_prev are
// cp.async-staged (safe here: all inputs were written by PRIOR launches).
__global__ void __launch_bounds__(128) k_step(const float* __restrict__ enc_h,
                                              const float* __restrict__ enc_c,
                                              const float* __restrict__ W_hh,
                                              int t) {
    extern __shared__ float sm[];
    float* w_sh    = sm;                 // [16][516]
    float* h_sh    = sm + 16 * 516;      // [16][516]  (b-major, padded)
    float* gate_sh = sm + 32 * 516;      // [16][16]   (rl = gate*4+jj, b)
    const uint32_t sb_w = smem_u32(w_sh);
    const uint32_t sb_h = smem_u32(h_sh);

    const int cb  = blockIdx.x;
    const int tid = threadIdx.x;

    // ---- stage W slice + h_prev via cp.async (one group) ----
    const float* hsrc = (t == 0) ? enc_h : &g_Hs[(size_t)(t - 1) * BB * HH];
#pragma unroll
    for (int i = 0; i < 16; i++) {
        int idx = tid + i * 128;               // 0..2047 float4 slots
        int row = idx >> 7, k4 = (idx & 127) << 2;
        int grow = (row >> 2) * HH + cb * 4 + (row & 3);
        cpasync16(sb_w + (uint32_t)(row * 516 + k4) * 4, W_hh + (size_t)grow * HH + k4);
        cpasync16(sb_h + (uint32_t)(row * 516 + k4) * 4, hsrc + row * HH + k4);
    }
    cp_commit();

    const int rp = tid >> 4;
    const int b  = tid & 15;
    const int r0 = rp * 2, r1 = r0 + 1;
    const int g0 = r0 >> 2, j0 = r0 & 3;
    const int g1 = r1 >> 2, j1 = r1 & 3;

    // overlap with cp.async flight: accumulator init + cell state
    float acc0 = g_Xg[(size_t)(t * BB + b) * G4 + g0 * HH + cb * 4 + j0];
    float acc1 = g_Xg[(size_t)(t * BB + b) * G4 + g1 * HH + cb * 4 + j1];
    float cprev = 0.0f;
    if (tid < 64) {
        int jj = tid >> 4, bb = tid & 15;
        cprev = (t == 0) ? enc_c[bb * HH + cb * 4 + jj]
                         : g_C[bb * HH + cb * 4 + jj];
    }

    cp_wait<0>();
    __syncthreads();

    const float* hp = &h_sh[b * 516];
    const float* w0 = &w_sh[r0 * 516];
    const float* w1 = &w_sh[r1 * 516];
#pragma unroll 8
    for (int k = 0; k < HH; k += 4) {
        float4 hv = *(const float4*)&hp[k];
        float4 wa = *(const float4*)&w0[k];
        float4 wb = *(const float4*)&w1[k];
        acc0 += hv.x * wa.x + hv.y * wa.y + hv.z * wa.z + hv.w * wa.w;
        acc1 += hv.x * wb.x + hv.y * wb.y + hv.z * wb.z + hv.w * wb.w;
    }
    gate_sh[r0 * 16 + b] = acc0;
    gate_sh[r1 * 16 + b] = acc1;
    __syncthreads();

    if (tid < 64) {
        int jj = tid >> 4, bb = tid & 15;
        float iv = sigm (gate_sh[(0 * 4 + jj) * 16 + bb]);
        float fv = sigm (gate_sh[(1 * 4 + jj) * 16 + bb]);
        float gv = tanhf(gate_sh[(2 * 4 + jj) * 16 + bb]);
        float ov = sigm (gate_sh[(3 * 4 + jj) * 16 + bb]);
        float cc = fv * cprev + iv * gv;
        g_C[bb * HH + cb * 4 + jj] = cc;
        float hv = ov * tanhf(cc);
        int hidx = (t * BB + bb) * HH + cb * 4 + jj;
        g_Hs[hidx] = hv;
        __nv_bfloat16 hb = __float2bfloat16(hv);
        g_Hh[hidx] = hb;
        g_Hl[hidx] = __float2bfloat16(hv - __bfloat162float(hb));
    }
}

// ---------------- launcher -------------------------------------------------
extern "C" void kernel_launch(void* const* d_in, const int* in_sizes, int n_in,
                              void* d_out, int out_size) {
    const int*   xs    = (const int*)  d_in[0];
    // d_in[1] = xs_len (unused by reference semantics)
    const float* enc_h = (const float*)d_in[2];
    const float* enc_c = (const float*)d_in[3];
    const float* emb   = (const float*)d_in[4];
    const float* W_ih  = (const float*)d_in[5];
    const float* W_hh  = (const float*)d_in[6];
    const float* b_ih  = (const float*)d_in[7];
    const float* b_hh  = (const float*)d_in[8];
    const float* W_out = (const float*)d_in[9];
    const float* b_out = (const float*)d_in[10];
    float* out = (float*)d_out;

    __nv_bfloat16 *pXh, *pXl, *pWih_h, *pWih_l, *pWout_h, *pWout_l, *pHh, *pHl;
    float *pXg, *pbias;
    cudaGetSymbolAddress((void**)&pXh,     g_Xh);
    cudaGetSymbolAddress((void**)&pXl,     g_Xl);
    cudaGetSymbolAddress((void**)&pWih_h,  g_Wih_h);
    cudaGetSymbolAddress((void**)&pWih_l,  g_Wih_l);
    cudaGetSymbolAddress((void**)&pWout_h, g_Wout_h);
    cudaGetSymbolAddress((void**)&pWout_l, g_Wout_l);
    cudaGetSymbolAddress((void**)&pHh,     g_Hh);
    cudaGetSymbolAddress((void**)&pHl,     g_Hl);
    cudaGetSymbolAddress((void**)&pXg,     g_Xg);
    cudaGetSymbolAddress((void**)&pbias,   g_bias);

    k_gather<<<1024, 256>>>(xs, emb);
    k_prep<<<8, 256>>>(b_ih, b_hh);
    k_conv<<<(G4*HH/4 + (int)((size_t)VV*HH/4)) / 256, 256>>>(W_ih, W_out);

    cudaFuncSetAttribute(gemm_tc, cudaFuncAttributeMaxDynamicSharedMemorySize, GSMEM);

    // Xg = X @ W_ih^T + (b_ih + b_hh)   [2048 x 2048]
    gemm_tc<<<dim3(G4 / 128, (TT * BB) / 128), 256, GSMEM>>>(
        pXh, pXl, pWih_h, pWih_l, pbias, pXg, G4);

    // LSTM: 128 per-step launches (launch boundary = grid barrier)
    int lsmem = (32 * 516 + 256) * (int)sizeof(float);  // ~67 KB
    cudaFuncSetAttribute(k_step, cudaFuncAttributeMaxDynamicSharedMemorySize, lsmem);
    for (int t = 0; t < TT; t++)
        k_step<<<128, 128, lsmem>>>(enc_h, enc_c, W_hh, t);

    // logits = Hs @ W_out^T + b_out     [2048 x 32000]
    gemm_tc<<<dim3(VV / 128, (TT * BB) / 128), 256, GSMEM>>>(
        pHh, pHl, pWout_h, pWout_l, b_out, out, VV);
}

// round 11
// speedup vs baseline: 1.9663x; 1.2651x over previous
#include <cuda_runtime.h>
#include <cuda_bf16.h>
#include <cstdint>

// Problem dims (fixed by the reference)
#define BB 16
#define TT 128
#define HH 512
#define VV 32000
#define G4 2048   // 4*H

// ---------------- device scratch (static: no allocation allowed) -----------
__device__ __nv_bfloat16 g_Xh   [TT*BB*HH];  // x embeddings, bf16 hi
__device__ __nv_bfloat16 g_Xl   [TT*BB*HH];  // x embeddings, bf16 lo
__device__ __nv_bfloat16 g_Wih_h[G4*HH];
__device__ __nv_bfloat16 g_Wih_l[G4*HH];
__device__ __nv_bfloat16 g_Whh_h[G4*HH];     // W_hh bf16 hi (row-major [2048][512])
__device__ __nv_bfloat16 g_Whh_l[G4*HH];     // W_hh bf16 lo
__device__ __nv_bfloat16 g_Wout_h[(size_t)VV*HH];
__device__ __nv_bfloat16 g_Wout_l[(size_t)VV*HH];
__device__ __nv_bfloat16 g_Hh   [TT*BB*HH];  // hidden states bf16 hi
__device__ __nv_bfloat16 g_Hl   [TT*BB*HH];  // hidden states bf16 lo
__device__ __nv_bfloat16 g_Eh   [BB*HH];     // enc_h bf16 hi
__device__ __nv_bfloat16 g_El   [BB*HH];     // enc_h bf16 lo
__device__ float    g_Xg[TT*BB*G4];   // x@W_ih^T + b_ih + b_hh (f32)
__device__ float    g_C [BB*HH];      // cell state (persists across step launches)
__device__ float    g_bias[G4];       // b_ih + b_hh

// ---------------- helpers --------------------------------------------------
__device__ __forceinline__ float sigm(float x) { return 1.0f / (1.0f + expf(-x)); }

__device__ __forceinline__ uint32_t smem_u32(const void* p) {
    uint32_t a;
    asm("{ .reg .u64 t; cvta.to.shared.u64 t, %1; cvt.u32.u64 %0, t; }" : "=r"(a) : "l"(p));
    return a;
}
__device__ __forceinline__ uint32_t sw128(uint32_t b) { return b ^ ((b >> 3) & 0x70); }

__device__ __forceinline__ void cpasync16(uint32_t dst, const void* src) {
    asm volatile("cp.async.cg.shared.global [%0], [%1], 16;" :: "r"(dst), "l"(src) : "memory");
}
__device__ __forceinline__ void cp_commit() { asm volatile("cp.async.commit_group;" ::: "memory"); }
template<int N> __device__ __forceinline__ void cp_wait() {
    asm volatile("cp.async.wait_group %0;" :: "n"(N) : "memory");
}

__device__ __forceinline__ void ldsm4(uint32_t* r, uint32_t addr) {
    asm volatile("ldmatrix.sync.aligned.m8n8.x4.shared.b16 {%0,%1,%2,%3}, [%4];"
                 : "=r"(r[0]), "=r"(r[1]), "=r"(r[2]), "=r"(r[3]) : "r"(addr));
}
__device__ __forceinline__ void ldsm2(uint32_t* r, uint32_t addr) {
    asm volatile("ldmatrix.sync.aligned.m8n8.x2.shared.b16 {%0,%1}, [%2];"
                 : "=r"(r[0]), "=r"(r[1]) : "r"(addr));
}
__device__ __forceinline__ void mma16816(float* c, const uint32_t* a, const uint32_t* b) {
    asm volatile("mma.sync.aligned.m16n8k16.row.col.f32.bf16.bf16.f32 "
                 "{%0,%1,%2,%3}, {%4,%5,%6,%7}, {%8,%9}, {%0,%1,%2,%3};"
                 : "+f"(c[0]), "+f"(c[1]), "+f"(c[2]), "+f"(c[3])
                 : "r"(a[0]), "r"(a[1]), "r"(a[2]), "r"(a[3]), "r"(b[0]), "r"(b[1]));
}

// split one float4 into packed bf16 hi/lo pairs
__device__ __forceinline__ void split4(float4 v, uint2& hi, uint2& lo) {
    float xs[4] = {v.x, v.y, v.z, v.w};
    unsigned h[4], l[4];
#pragma unroll
    for (int q = 0; q < 4; q++) {
        __nv_bfloat16 hb = __float2bfloat16(xs[q]);
        __nv_bfloat16 lb = __float2bfloat16(xs[q] - __bfloat162float(hb));
        h[q] = *(unsigned short*)&hb;
        l[q] = *(unsigned short*)&lb;
    }
    hi.x = h[0] | (h[1] << 16); hi.y = h[2] | (h[3] << 16);
    lo.x = l[0] | (l[1] << 16); lo.y = l[2] | (l[3] << 16);
}

// ---------------- kernel 1: embedding gather + bf16 split -----------------
__global__ void k_gather(const int* __restrict__ xs, const float* __restrict__ emb) {
    int f = blockIdx.x * 256 + threadIdx.x;          // float4 id, 2048*128 total
    int row = f >> 7;
    int e   = (f & 127) << 2;
    int t = row >> 4, b = row & 15;
    int tok = xs[b * TT + t];
    float4 v = *(const float4*)&emb[(size_t)tok * HH + e];
    uint2 hi, lo; split4(v, hi, lo);
    *(uint2*)&g_Xh[row * HH + e] = hi;
    *(uint2*)&g_Xl[row * HH + e] = lo;
}

// ---------------- kernel 2: bias sum + enc_h bf16 split -------------------
// grid 8 x 256 = 2048 threads; i covers bias[2048] AND enc_h float4s [2048].
__global__ void k_prep(const float* __restrict__ b_ih, const float* __restrict__ b_hh,
                       const float* __restrict__ enc_h) {
    int i = blockIdx.x * 256 + threadIdx.x;
    g_bias[i] = b_ih[i] + b_hh[i];
    float4 v = *(const float4*)&enc_h[i * 4];
    uint2 hi, lo; split4(v, hi, lo);
    *(uint2*)&g_Eh[i * 4] = hi;
    *(uint2*)&g_El[i * 4] = lo;
}

// ---------------- kernel 3: weight bf16 hi/lo conversion ------------------
__global__ void k_conv(const float* __restrict__ W_ih, const float* __restrict__ W_hh,
                       const float* __restrict__ W_out) {
    int i4 = blockIdx.x * 256 + threadIdx.x;
    const int NIH = G4 * HH / 4;          // 262144 float4s
    const int NHH = G4 * HH / 4;          // 262144 float4s
    if (i4 < NIH) {
        float4 v = *(const float4*)&W_ih[(size_t)i4 * 4];
        uint2 h, l; split4(v, h, l);
        *(uint2*)&g_Wih_h[(size_t)i4 * 4] = h;
        *(uint2*)&g_Wih_l[(size_t)i4 * 4] = l;
    } else if (i4 < NIH + NHH) {
        size_t j = (size_t)(i4 - NIH);
        float4 v = *(const float4*)&W_hh[j * 4];
        uint2 h, l; split4(v, h, l);
        *(uint2*)&g_Whh_h[j * 4] = h;
        *(uint2*)&g_Whh_l[j * 4] = l;
    } else {
        size_t j = (size_t)(i4 - NIH - NHH);   // < 4,096,000
        float4 v = *(const float4*)&W_out[j * 4];
        uint2 h, l; split4(v, h, l);
        *(uint2*)&g_Wout_h[j * 4] = h;
        *(uint2*)&g_Wout_l[j * 4] = l;
    }
}

// ---------------- kernel 4: pipelined bf16x3 mma.sync GEMM ----------------
// (byte-identical to round-4/5/8 passing version)
#define KC 64
#define ST_AH 0
#define ST_AL 16384
#define ST_BH 32768
#define ST_BL 49152
#define STAGE_BYTES 65536
#define NSTAGE 3
#define GSMEM (NSTAGE * STAGE_BYTES)    // 192 KB

__global__ void __launch_bounds__(256, 1) gemm_tc(
    const __nv_bfloat16* __restrict__ Ah, const __nv_bfloat16* __restrict__ Al,
    const __nv_bfloat16* __restrict__ Bh, const __nv_bfloat16* __restrict__ Bl,
    const float* __restrict__ bias, float* __restrict__ C, int M)
{
    extern __shared__ char smem[];
    const uint32_t sb = smem_u32(smem);
    const int tid  = threadIdx.x;
    const int lane = tid & 31, wid = tid >> 5;
    const int warp_n = wid >> 2;
    const int warp_m = wid & 3;
    const int n0 = blockIdx.y * 128;
    const int m0 = blockIdx.x * 128;

    float c[4][4][4];
#pragma unroll
    for (int i = 0; i < 4; i++)
#pragma unroll
        for (int j = 0; j < 4; j++)
#pragma unroll
            for (int q = 0; q < 4; q++) c[i][j][q] = 0.0f;

    const int a_lr = lane & 7, a_sel = lane >> 3;
    const int a_row = (a_sel & 1) * 8 + a_lr;
    const int a_col = (a_sel >> 1) * 8;
    const int b_l   = lane & 15;
    const int b_row = b_l & 7;
    const int b_col = (b_l >> 3) * 8;

    auto load_chunk = [&](int cc) {
        const uint32_t sbase = sb + (uint32_t)(cc % NSTAGE) * STAGE_BYTES;
        const int kb = cc * KC;
#pragma unroll
        for (int i = 0; i < 4; i++) {
            int idx = tid + i * 256;
            int row = idx >> 3, seg = idx & 7;
            uint32_t sw = sw128((uint32_t)(row * 128 + seg * 16));
            size_t goa = (size_t)(n0 + row) * HH + kb + seg * 8;
            size_t gob = (size_t)(m0 + row) * HH + kb + seg * 8;
            cpasync16(sbase + ST_AH + sw, Ah + goa);
            cpasync16(sbase + ST_AL + sw, Al + goa);
            cpasync16(sbase + ST_BH + sw, Bh + gob);
            cpasync16(sbase + ST_BL + sw, Bl + gob);
        }
        cp_commit();
    };

    uint32_t ah[2][4][4], al[2][4][4], bh[2][4][2], bl[2][4][2];
    auto ldfrag = [&](int buf, uint32_t sbase, int kk) {
#pragma unroll
        for (int i = 0; i < 4; i++) {
            int r = warp_n * 64 + i * 16 + a_row;
            uint32_t sw = sw128((uint32_t)(r * 128 + (kk + a_col) * 2));
            ldsm4(ah[buf][i], sbase + ST_AH + sw);
            ldsm4(al[buf][i], sbase + ST_AL + sw);
        }
#pragma unroll
        for (int j = 0; j < 4; j++) {
            int r = warp_m * 32 + j * 8 + b_row;
            uint32_t sw = sw128((uint32_t)(r * 128 + (kk + b_col) * 2));
            ldsm2(bh[buf][j], sbase + ST_BH + sw);
            ldsm2(bl[buf][j], sbase + ST_BL + sw);
        }
    };

    load_chunk(0);
    load_chunk(1);

#pragma unroll 1
    for (int cc = 0; cc < 8; cc++) {
        if (cc < 7) cp_wait<1>(); else cp_wait<0>();
        __syncthreads();
        if (cc + 2 < 8) load_chunk(cc + 2);
        const uint32_t sbase = sb + (uint32_t)(cc % NSTAGE) * STAGE_BYTES;

        ldfrag(0, sbase, 0);
#pragma unroll
        for (int ki = 0; ki < 4; ki++) {
            if (ki < 3) ldfrag((ki + 1) & 1, sbase, (ki + 1) * 16);
            const int bf = ki & 1;
#pragma unroll
            for (int i = 0; i < 4; i++)
#pragma unroll
                for (int j = 0; j < 4; j++) {
                    mma16816(c[i][j], ah[bf][i], bh[bf][j]);
                    mma16816(c[i][j], ah[bf][i], bl[bf][j]);
                    mma16816(c[i][j], al[bf][i], bh[bf][j]);
                }
        }
    }

#pragma unroll
    for (int i = 0; i < 4; i++) {
        int n = n0 + warp_n * 64 + i * 16 + (lane >> 2);
#pragma unroll
        for (int j = 0; j < 4; j++) {
            int m = m0 + warp_m * 32 + j * 8 + ((lane & 3) << 1);
            float bx = bias[m], by = bias[m + 1];
            *(float2*)&C[(size_t)n * M + m]       = make_float2(c[i][j][0] + bx, c[i][j][1] + by);
            *(float2*)&C[(size_t)(n + 8) * M + m] = make_float2(c[i][j][2] + bx, c[i][j][3] + by);
        }
    }
}

// ---------------- kernel 5: ONE LSTM time step (tensor-core GEMV) ---------
// Launched 128 times inside the graph (launch boundary = grid barrier;
// correctness by construction — same as the R8 passing design).
// CTA cb owns 16 gate rows grow(rl) = (rl>>2)*512 + cb*4 + (rl&3).
// gates[16 x 16b] = Wtile[16 x 512] x h[16b x 512]^T computed as bf16x3
// (Wh*Hh + Wh*Hl + Wl*Hh) with fp32 accum in 3 independent mma chains.
// smem layout per operand: [8 chunks][16 rows][128B] sw128-swizzled —
// identical geometry to gemm_tc's stages, frag code is a crop of gemm_tc.
#define SW_H 0
#define SW_L 16384
#define SH_H 32768
#define SH_L 49152
#define SGATE 65536
#define SSMEM (65536 + 1024)

__global__ void __launch_bounds__(128) k_step(const float* __restrict__ enc_c, int t) {
    extern __shared__ char smem[];
    const uint32_t sb = smem_u32(smem);
    float* gate_sh = (float*)(smem + SGATE);   // [16 rows][16 b]
    const int cb   = blockIdx.x;
    const int tid  = threadIdx.x;
    const int wid  = tid >> 5, lane = tid & 31;

    const __nv_bfloat16* Hh = (t == 0) ? g_Eh : g_Hh + (size_t)(t - 1) * BB * HH;
    const __nv_bfloat16* Hl = (t == 0) ? g_El : g_Hl + (size_t)(t - 1) * BB * HH;

    // ---- stage W hi/lo + h hi/lo: 4096 x 16B segs, 32 per thread ----
#pragma unroll
    for (int u = 0; u < 32; u++) {
        int idx = tid + u * 128;               // 0..4095
        int arr = idx >> 10;                   // 0:Wh 1:Wl 2:Hh 3:Hl
        int r   = (idx >> 6) & 15;             // row within tile
        int s   = idx & 63;                    // 16B seg within row (512 bf16)
        uint32_t dst = sb + (uint32_t)arr * 16384
                     + (uint32_t)(s >> 3) * 2048
                     + sw128((uint32_t)(r * 128 + (s & 7) * 16));
        int grow = (r >> 2) * HH + cb * 4 + (r & 3);
        const void* src;
        if      (arr == 0) src = g_Whh_h + (size_t)grow * HH + s * 8;
        else if (arr == 1) src = g_Whh_l + (size_t)grow * HH + s * 8;
        else if (arr == 2) src = Hh + r * HH + s * 8;
        else               src = Hl + r * HH + s * 8;
        cpasync16(dst, src);
    }
    cp_commit();

    // overlap: cell state load
    float cprev = 0.0f;
    if (tid < 64) {
        int jj = tid >> 4, bb = tid & 15;
        cprev = (t == 0) ? enc_c[bb * HH + cb * 4 + jj]
                         : g_C[bb * HH + cb * 4 + jj];
    }

    cp_wait<0>();
    __syncthreads();

    // ---- mma: warp w handles b-half w (j = w), 3 independent chains ----
    if (wid < 2) {
        const int a_lr = lane & 7, a_sel = lane >> 3;
        const int a_row = (a_sel & 1) * 8 + a_lr;
        const int a_col = (a_sel >> 1) * 8;
        const int b_l   = lane & 15;
        const int b_row = b_l & 7;
        const int b_col = (b_l >> 3) * 8;
        const int jrow  = wid * 8;

        float c1[4] = {0,0,0,0}, c2[4] = {0,0,0,0}, c3[4] = {0,0,0,0};
#pragma unroll
        for (int cc = 0; cc < 8; cc++) {
            uint32_t base = (uint32_t)cc * 2048;
#pragma unroll
            for (int kk = 0; kk < 64; kk += 16) {
                uint32_t ah[4], al[4], bh[2], bl[2];
                uint32_t wa = sw128((uint32_t)(a_row * 128 + (kk + a_col) * 2));
                ldsm4(ah, sb + SW_H + base + wa);
                ldsm4(al, sb + SW_L + base + wa);
                uint32_t hb = sw128((uint32_t)((jrow + b_row) * 128 + (kk + b_col) * 2));
                ldsm2(bh, sb + SH_H + base + hb);
                ldsm2(bl, sb + SH_L + base + hb);
                mma16816(c1, ah, bh);
                mma16816(c2, ah, bl);
                mma16816(c3, al, bh);
            }
        }
        int rl = lane >> 2;
        int b  = jrow + (lane & 3) * 2;
        gate_sh[rl * 16 + b]           = c1[0] + c2[0] + c3[0];
        gate_sh[rl * 16 + b + 1]       = c1[1] + c2[1] + c3[1];
        gate_sh[(rl + 8) * 16 + b]     = c1[2] + c2[2] + c3[2];
        gate_sh[(rl + 8) * 16 + b + 1] = c1[3] + c2[3] + c3[3];
    }
    __syncthreads();

    // ---- activations + cell update + bf16 hi/lo h store ----
    if (tid < 64) {
        int jj = tid >> 4, bb = tid & 15;
        const float* xg = g_Xg + (size_t)(t * BB + bb) * G4 + cb * 4 + jj;
        float iv = sigm (gate_sh[(0 * 4 + jj) * 16 + bb] + xg[0 * HH]);
        float fv = sigm (gate_sh[(1 * 4 + jj) * 16 + bb] + xg[1 * HH]);
        float gv = tanhf(gate_sh[(2 * 4 + jj) * 16 + bb] + xg[2 * HH]);
        float ov = sigm (gate_sh[(3 * 4 + jj) * 16 + bb] + xg[3 * HH]);
        float cc = fv * cprev + iv * gv;
        g_C[bb * HH + cb * 4 + jj] = cc;
        float hv = ov * tanhf(cc);
        int hidx = (t * BB + bb) * HH + cb * 4 + jj;
        __nv_bfloat16 hb16 = __float2bfloat16(hv);
        g_Hh[hidx] = hb16;
        g_Hl[hidx] = __float2bfloat16(hv - __bfloat162float(hb16));
    }
}

// ---------------- launcher -------------------------------------------------
extern "C" void kernel_launch(void* const* d_in, const int* in_sizes, int n_in,
                              void* d_out, int out_size) {
    const int*   xs    = (const int*)  d_in[0];
    // d_in[1] = xs_len (unused by reference semantics)
    const float* enc_h = (const float*)d_in[2];
    const float* enc_c = (const float*)d_in[3];
    const float* emb   = (const float*)d_in[4];
    const float* W_ih  = (const float*)d_in[5];
    const float* W_hh  = (const float*)d_in[6];
    const float* b_ih  = (const float*)d_in[7];
    const float* b_hh  = (const float*)d_in[8];
    const float* W_out = (const float*)d_in[9];
    const float* b_out = (const float*)d_in[10];
    float* out = (float*)d_out;

    __nv_bfloat16 *pXh, *pXl, *pWih_h, *pWih_l, *pWout_h, *pWout_l, *pHh, *pHl;
    float *pXg, *pbias;
    cudaGetSymbolAddress((void**)&pXh,     g_Xh);
    cudaGetSymbolAddress((void**)&pXl,     g_Xl);
    cudaGetSymbolAddress((void**)&pWih_h,  g_Wih_h);
    cudaGetSymbolAddress((void**)&pWih_l,  g_Wih_l);
    cudaGetSymbolAddress((void**)&pWout_h, g_Wout_h);
    cudaGetSymbolAddress((void**)&pWout_l, g_Wout_l);
    cudaGetSymbolAddress((void**)&pHh,     g_Hh);
    cudaGetSymbolAddress((void**)&pHl,     g_Hl);
    cudaGetSymbolAddress((void**)&pXg,     g_Xg);
    cudaGetSymbolAddress((void**)&pbias,   g_bias);

    k_gather<<<1024, 256>>>(xs, emb);
    k_prep<<<8, 256>>>(b_ih, b_hh, enc_h);
    k_conv<<<(2 * (G4 * HH / 4) + (int)((size_t)VV * HH / 4)) / 256, 256>>>(
        W_ih, W_hh, W_out);

    cudaFuncSetAttribute(gemm_tc, cudaFuncAttributeMaxDynamicSharedMemorySize, GSMEM);

    // Xg = X @ W_ih^T + (b_ih + b_hh)   [2048 x 2048]
    gemm_tc<<<dim3(G4 / 128, (TT * BB) / 128), 256, GSMEM>>>(
        pXh, pXl, pWih_h, pWih_l, pbias, pXg, G4);

    // LSTM: 128 per-step launches (launch boundary = grid barrier)
    cudaFuncSetAttribute(k_step, cudaFuncAttributeMaxDynamicSharedMemorySize, SSMEM);
    for (int t = 0; t < TT; t++)
        k_step<<<128, 128, SSMEM>>>(enc_c, t);

    // logits = Hs @ W_out^T + b_out     [2048 x 32000]
    gemm_tc<<<dim3(VV / 128, (TT * BB) / 128), 256, GSMEM>>>(
        pHh, pHl, pWout_h, pWout_l, b_out, out, VV);
}

// round 12
// speedup vs baseline: 2.0946x; 1.0652x over previous
#include <cuda_runtime.h>
#include <cuda_bf16.h>
#include <cstdint>

// Problem dims (fixed by the reference)
#define BB 16
#define TT 128
#define HH 512
#define VV 32000
#define G4 2048   // 4*H

// ---------------- device scratch (static: no allocation allowed) -----------
__device__ __nv_bfloat16 g_Xh   [TT*BB*HH];  // x embeddings, bf16 hi
__device__ __nv_bfloat16 g_Xl   [TT*BB*HH];  // x embeddings, bf16 lo
__device__ __nv_bfloat16 g_Wih_h[G4*HH];
__device__ __nv_bfloat16 g_Wih_l[G4*HH];
__device__ __nv_bfloat16 g_Whh_h[G4*HH];     // W_hh bf16 hi (row-major [2048][512])
__device__ __nv_bfloat16 g_Whh_l[G4*HH];     // W_hh bf16 lo
__device__ __nv_bfloat16 g_Wout_h[(size_t)VV*HH];
__device__ __nv_bfloat16 g_Wout_l[(size_t)VV*HH];
__device__ __nv_bfloat16 g_Hh   [TT*BB*HH];  // hidden states bf16 hi
__device__ __nv_bfloat16 g_Hl   [TT*BB*HH];  // hidden states bf16 lo
__device__ __nv_bfloat16 g_Eh   [BB*HH];     // enc_h bf16 hi
__device__ __nv_bfloat16 g_El   [BB*HH];     // enc_h bf16 lo
__device__ float    g_Xg[TT*BB*G4];   // x@W_ih^T + b_ih + b_hh (f32)
__device__ float    g_C [BB*HH];      // cell state (persists across step launches)
__device__ float    g_bias[G4];       // b_ih + b_hh

// ---------------- helpers --------------------------------------------------
__device__ __forceinline__ float sigm(float x) { return 1.0f / (1.0f + expf(-x)); }

__device__ __forceinline__ uint32_t smem_u32(const void* p) {
    uint32_t a;
    asm("{ .reg .u64 t; cvta.to.shared.u64 t, %1; cvt.u32.u64 %0, t; }" : "=r"(a) : "l"(p));
    return a;
}
__device__ __forceinline__ uint32_t sw128(uint32_t b) { return b ^ ((b >> 3) & 0x70); }

__device__ __forceinline__ void cpasync16(uint32_t dst, const void* src) {
    asm volatile("cp.async.cg.shared.global [%0], [%1], 16;" :: "r"(dst), "l"(src) : "memory");
}
__device__ __forceinline__ void cp_commit() { asm volatile("cp.async.commit_group;" ::: "memory"); }
template<int N> __device__ __forceinline__ void cp_wait() {
    asm volatile("cp.async.wait_group %0;" :: "n"(N) : "memory");
}

__device__ __forceinline__ void ldsm4(uint32_t* r, uint32_t addr) {
    asm volatile("ldmatrix.sync.aligned.m8n8.x4.shared.b16 {%0,%1,%2,%3}, [%4];"
                 : "=r"(r[0]), "=r"(r[1]), "=r"(r[2]), "=r"(r[3]) : "r"(addr));
}
__device__ __forceinline__ void ldsm2(uint32_t* r, uint32_t addr) {
    asm volatile("ldmatrix.sync.aligned.m8n8.x2.shared.b16 {%0,%1}, [%2];"
                 : "=r"(r[0]), "=r"(r[1]) : "r"(addr));
}
__device__ __forceinline__ void mma16816(float* c, const uint32_t* a, const uint32_t* b) {
    asm volatile("mma.sync.aligned.m16n8k16.row.col.f32.bf16.bf16.f32 "
                 "{%0,%1,%2,%3}, {%4,%5,%6,%7}, {%8,%9}, {%0,%1,%2,%3};"
                 : "+f"(c[0]), "+f"(c[1]), "+f"(c[2]), "+f"(c[3])
                 : "r"(a[0]), "r"(a[1]), "r"(a[2]), "r"(a[3]), "r"(b[0]), "r"(b[1]));
}

// split one float4 into packed bf16 hi/lo pairs
__device__ __forceinline__ void split4(float4 v, uint2& hi, uint2& lo) {
    float xs[4] = {v.x, v.y, v.z, v.w};
    unsigned h[4], l[4];
#pragma unroll
    for (int q = 0; q < 4; q++) {
        __nv_bfloat16 hb = __float2bfloat16(xs[q]);
        __nv_bfloat16 lb = __float2bfloat16(xs[q] - __bfloat162float(hb));
        h[q] = *(unsigned short*)&hb;
        l[q] = *(unsigned short*)&lb;
    }
    hi.x = h[0] | (h[1] << 16); hi.y = h[2] | (h[3] << 16);
    lo.x = l[0] | (l[1] << 16); lo.y = l[2] | (l[3] << 16);
}

// ---------------- kernel 1: embedding gather + bf16 split -----------------
__global__ void k_gather(const int* __restrict__ xs, const float* __restrict__ emb) {
    int f = blockIdx.x * 256 + threadIdx.x;          // float4 id, 2048*128 total
    int row = f >> 7;
    int e   = (f & 127) << 2;
    int t = row >> 4, b = row & 15;
    int tok = xs[b * TT + t];
    float4 v = *(const float4*)&emb[(size_t)tok * HH + e];
    uint2 hi, lo; split4(v, hi, lo);
    *(uint2*)&g_Xh[row * HH + e] = hi;
    *(uint2*)&g_Xl[row * HH + e] = lo;
}

// ---------------- kernel 2: bias sum + enc_h bf16 split -------------------
// grid 8 x 256 = 2048 threads; i covers bias[2048] AND enc_h float4s [2048].
__global__ void k_prep(const float* __restrict__ b_ih, const float* __restrict__ b_hh,
                       const float* __restrict__ enc_h) {
    int i = blockIdx.x * 256 + threadIdx.x;
    g_bias[i] = b_ih[i] + b_hh[i];
    float4 v = *(const float4*)&enc_h[i * 4];
    uint2 hi, lo; split4(v, hi, lo);
    *(uint2*)&g_Eh[i * 4] = hi;
    *(uint2*)&g_El[i * 4] = lo;
}

// ---------------- kernel 3: weight bf16 hi/lo conversion ------------------
__global__ void k_conv(const float* __restrict__ W_ih, const float* __restrict__ W_hh,
                       const float* __restrict__ W_out) {
    int i4 = blockIdx.x * 256 + threadIdx.x;
    const int NIH = G4 * HH / 4;          // 262144 float4s
    const int NHH = G4 * HH / 4;          // 262144 float4s
    if (i4 < NIH) {
        float4 v = *(const float4*)&W_ih[(size_t)i4 * 4];
        uint2 h, l; split4(v, h, l);
        *(uint2*)&g_Wih_h[(size_t)i4 * 4] = h;
        *(uint2*)&g_Wih_l[(size_t)i4 * 4] = l;
    } else if (i4 < NIH + NHH) {
        size_t j = (size_t)(i4 - NIH);
        float4 v = *(const float4*)&W_hh[j * 4];
        uint2 h, l; split4(v, h, l);
        *(uint2*)&g_Whh_h[j * 4] = h;
        *(uint2*)&g_Whh_l[j * 4] = l;
    } else {
        size_t j = (size_t)(i4 - NIH - NHH);   // < 4,096,000
        float4 v = *(const float4*)&W_out[j * 4];
        uint2 h, l; split4(v, h, l);
        *(uint2*)&g_Wout_h[j * 4] = h;
        *(uint2*)&g_Wout_l[j * 4] = l;
    }
}

// ---------------- kernel 4: pipelined bf16x3 mma.sync GEMM ----------------
// (byte-identical to round-4/5/8/11 passing version)
#define KC 64
#define ST_AH 0
#define ST_AL 16384
#define ST_BH 32768
#define ST_BL 49152
#define STAGE_BYTES 65536
#define NSTAGE 3
#define GSMEM (NSTAGE * STAGE_BYTES)    // 192 KB

__global__ void __launch_bounds__(256, 1) gemm_tc(
    const __nv_bfloat16* __restrict__ Ah, const __nv_bfloat16* __restrict__ Al,
    const __nv_bfloat16* __restrict__ Bh, const __nv_bfloat16* __restrict__ Bl,
    const float* __restrict__ bias, float* __restrict__ C, int M)
{
    extern __shared__ char smem[];
    const uint32_t sb = smem_u32(smem);
    const int tid  = threadIdx.x;
    const int lane = tid & 31, wid = tid >> 5;
    const int warp_n = wid >> 2;
    const int warp_m = wid & 3;
    const int n0 = blockIdx.y * 128;
    const int m0 = blockIdx.x * 128;

    float c[4][4][4];
#pragma unroll
    for (int i = 0; i < 4; i++)
#pragma unroll
        for (int j = 0; j < 4; j++)
#pragma unroll
            for (int q = 0; q < 4; q++) c[i][j][q] = 0.0f;

    const int a_lr = lane & 7, a_sel = lane >> 3;
    const int a_row = (a_sel & 1) * 8 + a_lr;
    const int a_col = (a_sel >> 1) * 8;
    const int b_l   = lane & 15;
    const int b_row = b_l & 7;
    const int b_col = (b_l >> 3) * 8;

    auto load_chunk = [&](int cc) {
        const uint32_t sbase = sb + (uint32_t)(cc % NSTAGE) * STAGE_BYTES;
        const int kb = cc * KC;
#pragma unroll
        for (int i = 0; i < 4; i++) {
            int idx = tid + i * 256;
            int row = idx >> 3, seg = idx & 7;
            uint32_t sw = sw128((uint32_t)(row * 128 + seg * 16));
            size_t goa = (size_t)(n0 + row) * HH + kb + seg * 8;
            size_t gob = (size_t)(m0 + row) * HH + kb + seg * 8;
            cpasync16(sbase + ST_AH + sw, Ah + goa);
            cpasync16(sbase + ST_AL + sw, Al + goa);
            cpasync16(sbase + ST_BH + sw, Bh + gob);
            cpasync16(sbase + ST_BL + sw, Bl + gob);
        }
        cp_commit();
    };

    uint32_t ah[2][4][4], al[2][4][4], bh[2][4][2], bl[2][4][2];
    auto ldfrag = [&](int buf, uint32_t sbase, int kk) {
#pragma unroll
        for (int i = 0; i < 4; i++) {
            int r = warp_n * 64 + i * 16 + a_row;
            uint32_t sw = sw128((uint32_t)(r * 128 + (kk + a_col) * 2));
            ldsm4(ah[buf][i], sbase + ST_AH + sw);
            ldsm4(al[buf][i], sbase + ST_AL + sw);
        }
#pragma unroll
        for (int j = 0; j < 4; j++) {
            int r = warp_m * 32 + j * 8 + b_row;
            uint32_t sw = sw128((uint32_t)(r * 128 + (kk + b_col) * 2));
            ldsm2(bh[buf][j], sbase + ST_BH + sw);
            ldsm2(bl[buf][j], sbase + ST_BL + sw);
        }
    };

    load_chunk(0);
    load_chunk(1);

#pragma unroll 1
    for (int cc = 0; cc < 8; cc++) {
        if (cc < 7) cp_wait<1>(); else cp_wait<0>();
        __syncthreads();
        if (cc + 2 < 8) load_chunk(cc + 2);
        const uint32_t sbase = sb + (uint32_t)(cc % NSTAGE) * STAGE_BYTES;

        ldfrag(0, sbase, 0);
#pragma unroll
        for (int ki = 0; ki < 4; ki++) {
            if (ki < 3) ldfrag((ki + 1) & 1, sbase, (ki + 1) * 16);
            const int bf = ki & 1;
#pragma unroll
            for (int i = 0; i < 4; i++)
#pragma unroll
                for (int j = 0; j < 4; j++) {
                    mma16816(c[i][j], ah[bf][i], bh[bf][j]);
                    mma16816(c[i][j], ah[bf][i], bl[bf][j]);
                    mma16816(c[i][j], al[bf][i], bh[bf][j]);
                }
        }
    }

#pragma unroll
    for (int i = 0; i < 4; i++) {
        int n = n0 + warp_n * 64 + i * 16 + (lane >> 2);
#pragma unroll
        for (int j = 0; j < 4; j++) {
            int m = m0 + warp_m * 32 + j * 8 + ((lane & 3) << 1);
            float bx = bias[m], by = bias[m + 1];
            *(float2*)&C[(size_t)n * M + m]       = make_float2(c[i][j][0] + bx, c[i][j][1] + by);
            *(float2*)&C[(size_t)(n + 8) * M + m] = make_float2(c[i][j][2] + bx, c[i][j][3] + by);
        }
    }
}

// ---------------- kernel 5: ONE LSTM time step (tensor-core GEMV) ---------
// Launched 128 times with PDL (programmatic dependent launch): the driver
// rolls out grid t+1 while grid t executes; griddepcontrol.wait (first
// instruction) blocks until grid t's memory is visible — the SAME
// happens-before edge as a plain launch boundary, with the ~2us setup
// hidden. Without the PDL attribute (correctness run / fallback) the wait
// is a defined no-op and ordering comes from the stream.
#define SW_H 0
#define SW_L 16384
#define SH_H 32768
#define SH_L 49152
#define SGATE 65536
#define SSMEM (65536 + 1024)

__global__ void __launch_bounds__(128) k_step(const float* __restrict__ enc_c, int t) {
    asm volatile("griddepcontrol.wait;" ::: "memory");   // predecessor grid visible

    extern __shared__ char smem[];
    const uint32_t sb = smem_u32(smem);
    float* gate_sh = (float*)(smem + SGATE);   // [16 rows][16 b]
    const int cb   = blockIdx.x;
    const int tid  = threadIdx.x;
    const int wid  = tid >> 5, lane = tid & 31;

    const __nv_bfloat16* Hh = (t == 0) ? g_Eh : g_Hh + (size_t)(t - 1) * BB * HH;
    const __nv_bfloat16* Hl = (t == 0) ? g_El : g_Hl + (size_t)(t - 1) * BB * HH;

    // ---- stage W hi/lo + h hi/lo: 4096 x 16B segs, 32 per thread ----
#pragma unroll
    for (int u = 0; u < 32; u++) {
        int idx = tid + u * 128;               // 0..4095
        int arr = idx >> 10;                   // 0:Wh 1:Wl 2:Hh 3:Hl
        int r   = (idx >> 6) & 15;             // row within tile
        int s   = idx & 63;                    // 16B seg within row (512 bf16)
        uint32_t dst = sb + (uint32_t)arr * 16384
                     + (uint32_t)(s >> 3) * 2048
                     + sw128((uint32_t)(r * 128 + (s & 7) * 16));
        int grow = (r >> 2) * HH + cb * 4 + (r & 3);
        const void* src;
        if      (arr == 0) src = g_Whh_h + (size_t)grow * HH + s * 8;
        else if (arr == 1) src = g_Whh_l + (size_t)grow * HH + s * 8;
        else if (arr == 2) src = Hh + r * HH + s * 8;
        else               src = Hl + r * HH + s * 8;
        cpasync16(dst, src);
    }
    cp_commit();

    // overlap: cell state load
    float cprev = 0.0f;
    if (tid < 64) {
        int jj = tid >> 4, bb = tid & 15;
        cprev = (t == 0) ? enc_c[bb * HH + cb * 4 + jj]
                         : g_C[bb * HH + cb * 4 + jj];
    }

    cp_wait<0>();
    __syncthreads();

    // ---- mma: warp w handles b-half w (j = w), 3 independent chains ----
    if (wid < 2) {
        const int a_lr = lane & 7, a_sel = lane >> 3;
        const int a_row = (a_sel & 1) * 8 + a_lr;
        const int a_col = (a_sel >> 1) * 8;
        const int b_l   = lane & 15;
        const int b_row = b_l & 7;
        const int b_col = (b_l >> 3) * 8;
        const int jrow  = wid * 8;

        float c1[4] = {0,0,0,0}, c2[4] = {0,0,0,0}, c3[4] = {0,0,0,0};
#pragma unroll
        for (int cc = 0; cc < 8; cc++) {
            uint32_t base = (uint32_t)cc * 2048;
#pragma unroll
            for (int kk = 0; kk < 64; kk += 16) {
                uint32_t ah[4], al[4], bh[2], bl[2];
                uint32_t wa = sw128((uint32_t)(a_row * 128 + (kk + a_col) * 2));
                ldsm4(ah, sb + SW_H + base + wa);
                ldsm4(al, sb + SW_L + base + wa);
                uint32_t hb = sw128((uint32_t)((jrow + b_row) * 128 + (kk + b_col) * 2));
                ldsm2(bh, sb + SH_H + base + hb);
                ldsm2(bl, sb + SH_L + base + hb);
                mma16816(c1, ah, bh);
                mma16816(c2, ah, bl);
                mma16816(c3, al, bh);
            }
        }
        int rl = lane >> 2;
        int b  = jrow + (lane & 3) * 2;
        gate_sh[rl * 16 + b]           = c1[0] + c2[0] + c3[0];
        gate_sh[rl * 16 + b + 1]       = c1[1] + c2[1] + c3[1];
        gate_sh[(rl + 8) * 16 + b]     = c1[2] + c2[2] + c3[2];
        gate_sh[(rl + 8) * 16 + b + 1] = c1[3] + c2[3] + c3[3];
    }
    __syncthreads();

    // ---- activations + cell update + bf16 hi/lo h store ----
    if (tid < 64) {
        int jj = tid >> 4, bb = tid & 15;
        const float* xg = g_Xg + (size_t)(t * BB + bb) * G4 + cb * 4 + jj;
        float iv = sigm (gate_sh[(0 * 4 + jj) * 16 + bb] + xg[0 * HH]);
        float fv = sigm (gate_sh[(1 * 4 + jj) * 16 + bb] + xg[1 * HH]);
        float gv = tanhf(gate_sh[(2 * 4 + jj) * 16 + bb] + xg[2 * HH]);
        float ov = sigm (gate_sh[(3 * 4 + jj) * 16 + bb] + xg[3 * HH]);
        float cc = fv * cprev + iv * gv;
        g_C[bb * HH + cb * 4 + jj] = cc;
        float hv = ov * tanhf(cc);
        int hidx = (t * BB + bb) * HH + cb * 4 + jj;
        __nv_bfloat16 hb16 = __float2bfloat16(hv);
        g_Hh[hidx] = hb16;
        g_Hl[hidx] = __float2bfloat16(hv - __bfloat162float(hb16));
    }
}

// ---------------- launcher -------------------------------------------------
extern "C" void kernel_launch(void* const* d_in, const int* in_sizes, int n_in,
                              void* d_out, int out_size) {
    const int*   xs    = (const int*)  d_in[0];
    // d_in[1] = xs_len (unused by reference semantics)
    const float* enc_h = (const float*)d_in[2];
    const float* enc_c = (const float*)d_in[3];
    const float* emb   = (const float*)d_in[4];
    const float* W_ih  = (const float*)d_in[5];
    const float* W_hh  = (const float*)d_in[6];
    const float* b_ih  = (const float*)d_in[7];
    const float* b_hh  = (const float*)d_in[8];
    const float* W_out = (const float*)d_in[9];
    const float* b_out = (const float*)d_in[10];
    float* out = (float*)d_out;

    __nv_bfloat16 *pXh, *pXl, *pWih_h, *pWih_l, *pWout_h, *pWout_l, *pHh, *pHl;
    float *pXg, *pbias;
    cudaGetSymbolAddress((void**)&pXh,     g_Xh);
    cudaGetSymbolAddress((void**)&pXl,     g_Xl);
    cudaGetSymbolAddress((void**)&pWih_h,  g_Wih_h);
    cudaGetSymbolAddress((void**)&pWih_l,  g_Wih_l);
    cudaGetSymbolAddress((void**)&pWout_h, g_Wout_h);
    cudaGetSymbolAddress((void**)&pWout_l, g_Wout_l);
    cudaGetSymbolAddress((void**)&pHh,     g_Hh);
    cudaGetSymbolAddress((void**)&pHl,     g_Hl);
    cudaGetSymbolAddress((void**)&pXg,     g_Xg);
    cudaGetSymbolAddress((void**)&pbias,   g_bias);

    k_gather<<<1024, 256>>>(xs, emb);
    k_prep<<<8, 256>>>(b_ih, b_hh, enc_h);
    k_conv<<<(2 * (G4 * HH / 4) + (int)((size_t)VV * HH / 4)) / 256, 256>>>(
        W_ih, W_hh, W_out);

    cudaFuncSetAttribute(gemm_tc, cudaFuncAttributeMaxDynamicSharedMemorySize, GSMEM);

    // Xg = X @ W_ih^T + (b_ih + b_hh)   [2048 x 2048]
    gemm_tc<<<dim3(G4 / 128, (TT * BB) / 128), 256, GSMEM>>>(
        pXh, pXl, pWih_h, pWih_l, pbias, pXg, G4);

    // LSTM: 128 per-step launches with PDL so launch setup overlaps the
    // previous step's execution. Fallback to plain launches keeps the graph
    // valid (and correct) if PDL-in-capture is unsupported.
    cudaFuncSetAttribute(k_step, cudaFuncAttributeMaxDynamicSharedMemorySize, SSMEM);
    cudaLaunchConfig_t cfg = {};
    cfg.gridDim = dim3(128, 1, 1);
    cfg.blockDim = dim3(128, 1, 1);
    cfg.dynamicSmemBytes = SSMEM;
    cfg.stream = 0;                      // legacy default stream (captured)
    cudaLaunchAttribute attr[1];
    attr[0].id = cudaLaunchAttributeProgrammaticStreamSerialization;
    attr[0].val.programmaticStreamSerializationAllowed = 1;
    cfg.attrs = attr;
    cfg.numAttrs = 1;
    for (int t = 0; t < TT; t++) {
        if (cudaLaunchKernelEx(&cfg, k_step, (const float*)enc_c, t) != cudaSuccess)
            k_step<<<128, 128, SSMEM>>>(enc_c, t);
    }

    // logits = Hs @ W_out^T + b_out     [2048 x 32000]
    gemm_tc<<<dim3(VV / 128, (TT * BB) / 128), 256, GSMEM>>>(
        pHh, pHl, pWout_h, pWout_l, b_out, out, VV);
}